// round 15
// baseline (speedup 1.0000x reference)
#include <cuda_runtime.h>
#include <cuda_bf16.h>
#include <math.h>
#include <stdint.h>

#define LSEQ 512
#define NB   64
#define KIN  38
#define EDIM 1024
#define HDIM 1024
#define NL   3
#define NC   38
#define H3   (3*HDIM)

#define GRU_BLOCKS 128
#define WS_LD 1032

// gru smem byte offsets
#define MB0_OFF   0
#define MB1_OFF   8
#define WS_HI_OFF 16
#define WS_LO_OFF (WS_HI_OFF + 24*WS_LD*2)     // 49552
#define HB_OFF    (WS_LO_OFF + 24*WS_LD*2)     // 99088
#define RED_OFF   (HB_OFF + 2*32768)           // 164624
#define SMOUT_OFF (RED_OFF + 6144)             // 170768
#define GRU_SMEM  (SMOUT_OFF + 2048)           // 172816

// h2 layout: [slot(2)][chunk(8)][split(2)][row(64)][col(128)] bf16,
// groups of 8 cols xor-swizzled by (row&7).
#define H2_SLOT 131072

// ---------------- scratch (device globals; no allocations allowed) ----------
__device__ __align__(16) float         g_xg[(size_t)LSEQ * NB * H3];
__device__ __align__(16) __nv_bfloat16 g_y_hi[(size_t)LSEQ * NB * EDIM];
__device__ __align__(16) __nv_bfloat16 g_y_lo[(size_t)LSEQ * NB * EDIM];
__device__ __align__(16) __nv_bfloat16 g_h2[2 * H2_SLOT];
__device__ __align__(16) __nv_bfloat16 g_wih_hi[(size_t)NL * H3 * EDIM];
__device__ __align__(16) __nv_bfloat16 g_wih_lo[(size_t)NL * H3 * EDIM];
__device__ __align__(16) __nv_bfloat16 g_whh_hi[(size_t)NL * H3 * HDIM];
__device__ __align__(16) __nv_bfloat16 g_whh_lo[(size_t)NL * H3 * HDIM];

// barrier flags (monotonic; generation derived from flag value => replay-safe)
__device__ unsigned g_flags[GRU_BLOCKS];

__device__ __forceinline__ void flag_barrier(int bid, unsigned target) {
    __syncthreads();
    if (threadIdx.x == 0) {
        __threadfence();
        ((volatile unsigned*)g_flags)[bid] = target;
    }
    if (threadIdx.x < 32) {
        bool done = false;
        while (!done) {
            bool ok = true;
#pragma unroll
            for (int q = 0; q < 4; q++) {
                unsigned v = ((volatile unsigned*)g_flags)[threadIdx.x + q * 32];
                if ((int)(v - target) < 0) ok = false;
            }
            done = __all_sync(0xffffffffu, ok);
        }
    }
    __syncthreads();
}

// ---------------- helpers ------------------------------------------------------
__device__ __forceinline__ uint32_t smem_u32(const void* p) {
    return (uint32_t)__cvta_generic_to_shared(p);
}
__device__ __forceinline__ void ldsm_x4(uint32_t* r, uint32_t addr) {
    asm volatile("ldmatrix.sync.aligned.m8n8.x4.shared.b16 {%0,%1,%2,%3},[%4];"
                 : "=r"(r[0]), "=r"(r[1]), "=r"(r[2]), "=r"(r[3]) : "r"(addr));
}
__device__ __forceinline__ void mma16816(float* c, const uint32_t* a,
                                         uint32_t b0, uint32_t b1) {
    asm volatile(
        "mma.sync.aligned.m16n8k16.row.col.f32.bf16.bf16.f32 "
        "{%0,%1,%2,%3},{%4,%5,%6,%7},{%8,%9},{%0,%1,%2,%3};"
        : "+f"(c[0]), "+f"(c[1]), "+f"(c[2]), "+f"(c[3])
        : "r"(a[0]), "r"(a[1]), "r"(a[2]), "r"(a[3]), "r"(b0), "r"(b1));
}
__device__ __forceinline__ void bulk_copy(uint32_t dst_smem, const void* src,
                                          uint32_t bytes, uint32_t mbar) {
    asm volatile(
        "cp.async.bulk.shared::cluster.global.mbarrier::complete_tx::bytes "
        "[%0], [%1], %2, [%3];"
        :: "r"(dst_smem), "l"(__cvta_generic_to_global(src)), "r"(bytes), "r"(mbar)
        : "memory");
}
#define MBARRIER_INIT(mb, cnt) \
    asm volatile("mbarrier.init.shared.b64 [%0], %1;" :: "r"((uint32_t)(mb)), "r"((uint32_t)(cnt)) : "memory")
#define MBARRIER_EXPECT_TX(mb, tx) \
    asm volatile("mbarrier.arrive.expect_tx.shared.b64 _, [%0], %1;" \
                 :: "r"((uint32_t)(mb)), "r"((uint32_t)(tx)) : "memory")
#define MBARRIER_WAIT_PARITY(mb, ph) do { \
    uint32_t _mb = (uint32_t)(mb), _ph = (uint32_t)(ph), _done; \
    asm volatile("{\n\t.reg .pred p;\n\t" \
        "mbarrier.try_wait.parity.acquire.cta.shared::cta.b64 p, [%1], %2;\n\t" \
        "selp.b32 %0, 1, 0, p;\n\t}" : "=r"(_done) : "r"(_mb), "r"(_ph) : "memory"); \
    if (!_done) { \
        asm volatile("{\n\t.reg .pred P1;\n\t" \
            "WAIT_LOOP_%=:\n\t" \
            "mbarrier.try_wait.parity.acquire.cta.shared::cta.b64 P1, [%0], %1, 0x989680;\n\t" \
            "@P1 bra.uni WAIT_DONE_%=;\n\tbra.uni WAIT_LOOP_%=;\n\tWAIT_DONE_%=:\n\t}" \
            :: "r"(_mb), "r"(_ph) : "memory"); \
    } \
} while (0)

__device__ __forceinline__ void split2(float x, __nv_bfloat16& hi, __nv_bfloat16& lo) {
    hi = __float2bfloat16(x);
    lo = __float2bfloat16(x - __bfloat162float(hi));
}
__device__ __forceinline__ float sigmoidf_(float x) {
    return 1.f / (1.f + expf(-x));
}

// ---------------- weight split ----------------------------------------------
__global__ void split_kernel(const float* __restrict__ src,
                             __nv_bfloat16* __restrict__ hi,
                             __nv_bfloat16* __restrict__ lo, int n) {
    for (int i = blockIdx.x * 256 + threadIdx.x; i < n; i += gridDim.x * 256) {
        float x = src[i];
        __nv_bfloat16 h = __float2bfloat16(x);
        hi[i] = h;
        lo[i] = __float2bfloat16(x - __bfloat162float(h));
    }
}

// ---------------- embedding ---------------------------------------------------
__global__ void embed_kernel(const float* __restrict__ in,
                             const float* __restrict__ W,
                             const float* __restrict__ b,
                             __nv_bfloat16* __restrict__ yhi,
                             __nv_bfloat16* __restrict__ ylo) {
    int ln = blockIdx.x;
    int e  = blockIdx.y * 256 + threadIdx.x;
    __shared__ float xs[KIN];
    if (threadIdx.x < KIN) xs[threadIdx.x] = in[(size_t)ln * KIN + threadIdx.x];
    __syncthreads();
    float acc = b[e];
    const float* w = W + (size_t)e * KIN;
#pragma unroll
    for (int k = 0; k < KIN; k++) acc = fmaf(xs[k], w[k], acc);
    __nv_bfloat16 hh, hl;
    split2(acc, hh, hl);
    yhi[(size_t)ln * EDIM + e] = hh;
    ylo[(size_t)ln * EDIM + e] = hl;
}

// ---------------- bf16-split MMA GEMM (input projections) --------------------
__global__ void __launch_bounds__(256)
gemm_xg_mma(const __nv_bfloat16* __restrict__ Ahi,
            const __nv_bfloat16* __restrict__ Alo,
            const __nv_bfloat16* __restrict__ Bhi,
            const __nv_bfloat16* __restrict__ Blo,
            const float* __restrict__ bias,
            float* __restrict__ C) {
    __shared__ __nv_bfloat16 sA[2][128][40];
    __shared__ __nv_bfloat16 sB[2][64][40];
    const int tid = threadIdx.x, lane = tid & 31, warp = tid >> 5;
    const int wm = warp >> 1, wn = warp & 1;
    const int bm = blockIdx.y * 128, bn = blockIdx.x * 64;

    float c[2][4][4];
#pragma unroll
    for (int m = 0; m < 2; m++)
#pragma unroll
        for (int n = 0; n < 4; n++)
#pragma unroll
            for (int q = 0; q < 4; q++) c[m][n][q] = 0.f;

    for (int k0 = 0; k0 < EDIM; k0 += 32) {
        __syncthreads();
        for (int i = tid; i < 512; i += 256) {
            int r = i >> 2, cv = i & 3;
            *(uint4*)&sA[0][r][cv * 8] = *(const uint4*)(Ahi + (size_t)(bm + r) * EDIM + k0 + cv * 8);
            *(uint4*)&sA[1][r][cv * 8] = *(const uint4*)(Alo + (size_t)(bm + r) * EDIM + k0 + cv * 8);
        }
        if (tid < 256) {
            int r = tid >> 2, cv = tid & 3;
            *(uint4*)&sB[0][r][cv * 8] = *(const uint4*)(Bhi + (size_t)(bn + r) * EDIM + k0 + cv * 8);
            *(uint4*)&sB[1][r][cv * 8] = *(const uint4*)(Blo + (size_t)(bn + r) * EDIM + k0 + cv * 8);
        }
        __syncthreads();

        uint32_t a[2][2][2][4];
#pragma unroll
        for (int s = 0; s < 2; s++)
#pragma unroll
            for (int m = 0; m < 2; m++) {
                int arow = wm * 32 + m * 16 + (lane & 15);
                int acol = (lane >> 4) * 8;
                uint32_t ad = smem_u32(&sA[s][arow][acol]);
                ldsm_x4(a[s][m][0], ad);
                ldsm_x4(a[s][m][1], ad + 32);
            }
        uint32_t bf[2][4][4];
#pragma unroll
        for (int s = 0; s < 2; s++)
#pragma unroll
            for (int n = 0; n < 4; n++) {
                int brow = wn * 32 + n * 8 + (lane & 7);
                int bcol = (lane >> 3) * 8;
                ldsm_x4(bf[s][n], smem_u32(&sB[s][brow][bcol]));
            }
#pragma unroll
        for (int m = 0; m < 2; m++)
#pragma unroll
            for (int n = 0; n < 4; n++)
#pragma unroll
                for (int k = 0; k < 2; k++) {
                    mma16816(c[m][n], a[0][m][k], bf[0][n][k * 2], bf[0][n][k * 2 + 1]);
                    mma16816(c[m][n], a[0][m][k], bf[1][n][k * 2], bf[1][n][k * 2 + 1]);
                    mma16816(c[m][n], a[1][m][k], bf[0][n][k * 2], bf[0][n][k * 2 + 1]);
                }
    }

#pragma unroll
    for (int m = 0; m < 2; m++) {
        int row0 = bm + wm * 32 + m * 16 + (lane >> 2);
#pragma unroll
        for (int n = 0; n < 4; n++) {
            int col = bn + wn * 32 + n * 8 + (lane & 3) * 2;
            float2 bb = *(const float2*)(bias + col);
            float2 v0 = make_float2(c[m][n][0] + bb.x, c[m][n][1] + bb.y);
            float2 v1 = make_float2(c[m][n][2] + bb.x, c[m][n][3] + bb.y);
            *(float2*)(C + (size_t)row0 * H3 + col) = v0;
            *(float2*)(C + (size_t)(row0 + 8) * H3 + col) = v1;
        }
    }
}

// ---------------- persistent GRU layer: bulk-DMA staged h ---------------------
// 256 threads (8 warps: 4 wm x 2 wk). Block owns 8 hidden cols (24 W rows,
// resident in smem). h broadcast: 8 chunks x 32KB per step, each ONE
// cp.async.bulk into a double buffer, completion via mbarrier.
__global__ void __launch_bounds__(256, 1)
gru_layer_mma(const float* __restrict__ xg,
              const __nv_bfloat16* __restrict__ whh_hi,
              const __nv_bfloat16* __restrict__ whh_lo,
              const float* __restrict__ bhh,
              __nv_bfloat16* __restrict__ h2,
              __nv_bfloat16* __restrict__ yhi,
              __nv_bfloat16* __restrict__ ylo) {
    extern __shared__ __align__(16) char smem[];
    __nv_bfloat16* ws_hi  = (__nv_bfloat16*)(smem + WS_HI_OFF);
    __nv_bfloat16* ws_lo  = (__nv_bfloat16*)(smem + WS_LO_OFF);
    float*         red    = (float*)(smem + RED_OFF);
    __nv_bfloat16* sm_out = (__nv_bfloat16*)(smem + SMOUT_OFF);
    const uint32_t smem_base = smem_u32(smem);
    const uint32_t hb_base = smem_base + HB_OFF;
    const uint32_t mb0 = smem_base + MB0_OFF;
    const uint32_t mb1 = smem_base + MB1_OFF;

    const int tid  = threadIdx.x;
    const int lane = tid & 31, warp = tid >> 5;
    const int wm = warp & 3, wk = warp >> 2;
    const int bid = blockIdx.x;
    const int j0 = bid * 8;
    const int g0 = (j0 >> 3) & 15;      // 16B group of this block's cols
    const int chn0 = j0 >> 7;           // chunk of this block's cols

    if (tid == 0) {
        MBARRIER_INIT(mb0, 1);
        MBARRIER_INIT(mb1, 1);
    }

    // W tile -> smem (rows r = g*8+jj -> global row g*HDIM + j0 + jj)
    for (int i = tid; i < 24 * 128; i += 256) {
        int r = i >> 7, v = i & 127;
        int grow = (r >> 3) * HDIM + j0 + (r & 7);
        *(uint4*)&ws_hi[r * WS_LD + v * 8] = *(const uint4*)(whh_hi + (size_t)grow * HDIM + v * 8);
        *(uint4*)&ws_lo[r * WS_LD + v * 8] = *(const uint4*)(whh_lo + (size_t)grow * HDIM + v * 8);
    }
    // zero h slot 0: block zeros its 1024-element slice
    *(uint2*)&h2[bid * 1024 + tid * 4] = make_uint2(0u, 0u);
    __syncthreads();

    unsigned bar_t = ((volatile unsigned*)g_flags)[bid];
    flag_barrier(bid, ++bar_t);

    int wc0 = 0, wc1 = 0;

    for (int t = 0; t < LSEQ; t++) {
        const __nv_bfloat16* hsrc = h2 + (size_t)(t & 1) * H2_SLOT;
        __nv_bfloat16* hdst = h2 + (size_t)((t + 1) & 1) * H2_SLOT;
        const float* xg_t = xg + (size_t)t * NB * H3;

        // kick off chunk 0 bulk copy
        if (tid == 0) {
            MBARRIER_EXPECT_TX(mb0, 32768);
            bulk_copy(hb_base, hsrc, 32768, mb0);
        }

        // prefetch epilogue operands (wk==0 warps do gates)
        float xr_[4], xz_[4], xn_[4], hp_[4];
        if (wk == 0) {
#pragma unroll
            for (int q = 0; q < 4; q++) {
                int b  = wm * 16 + (lane >> 2) + (q >> 1) * 8;
                int ja = j0 + (lane & 3) * 2 + (q & 1);
                const float* xr = xg_t + (size_t)b * H3 + ja;
                xr_[q] = xr[0];
                xz_[q] = xr[HDIM];
                xn_[q] = xr[2 * HDIM];
                int e = chn0 * 16384 + b * 128 + ((g0 ^ (b & 7)) << 3) + (ja & 7);
                hp_[q] = __bfloat162float(hsrc[e]) + __bfloat162float(hsrc[e + 8192]);
            }
        }

        float c[3][4];
#pragma unroll
        for (int i = 0; i < 3; i++)
#pragma unroll
            for (int q = 0; q < 4; q++) c[i][q] = 0.f;

        for (int ch = 0; ch < 8; ch++) {
            const int buf = ch & 1;
            // issue next chunk into the other buffer (free since chunk ch-1)
            if (ch < 7 && tid == 0) {
                uint32_t mbn = (buf == 0) ? mb1 : mb0;
                MBARRIER_EXPECT_TX(mbn, 32768);
                bulk_copy(hb_base + (1 - buf) * 32768,
                          hsrc + (size_t)(ch + 1) * 16384, 32768, mbn);
            }
            if (buf == 0) { MBARRIER_WAIT_PARITY(mb0, wc0 & 1); wc0++; }
            else          { MBARRIER_WAIT_PARITY(mb1, wc1 & 1); wc1++; }

            const uint32_t bufb = hb_base + buf * 32768;
            const int arow = wm * 16 + (lane & 15);
            const int rx = arow & 7;
            const uint32_t rowb = bufb + arow * 256;
#pragma unroll
            for (int k32 = 0; k32 < 2; k32++) {
                const int gb = wk * 8 + k32 * 4 + (lane >> 4);
                uint32_t a0 = rowb + (uint32_t)((gb ^ rx) << 4);
                uint32_t a1 = rowb + (uint32_t)(((gb + 2) ^ rx) << 4);
                uint32_t a_hi[2][4], a_lo[2][4];
                ldsm_x4(a_hi[0], a0);          ldsm_x4(a_hi[1], a1);
                ldsm_x4(a_lo[0], a0 + 16384);  ldsm_x4(a_lo[1], a1 + 16384);

                uint32_t b_hi[3][4], b_lo[3][4];
                int bkcol = ch * 128 + wk * 64 + k32 * 32 + (lane >> 3) * 8;
#pragma unroll
                for (int n8 = 0; n8 < 3; n8++) {
                    int brow = n8 * 8 + (lane & 7);
                    ldsm_x4(b_hi[n8], smem_u32(&ws_hi[brow * WS_LD + bkcol]));
                    ldsm_x4(b_lo[n8], smem_u32(&ws_lo[brow * WS_LD + bkcol]));
                }
#pragma unroll
                for (int n8 = 0; n8 < 3; n8++)
#pragma unroll
                    for (int k = 0; k < 2; k++) {
                        mma16816(c[n8], a_hi[k], b_hi[n8][k * 2], b_hi[n8][k * 2 + 1]);
                        mma16816(c[n8], a_hi[k], b_lo[n8][k * 2], b_lo[n8][k * 2 + 1]);
                        mma16816(c[n8], a_lo[k], b_hi[n8][k * 2], b_hi[n8][k * 2 + 1]);
                    }
            }
            __syncthreads();   // all warps done reading buf -> refillable
        }

        // combine k-halves
        if (wk == 1) {
            float* rp = red + ((size_t)wm * 32 + lane) * 12;
#pragma unroll
            for (int i = 0; i < 3; i++)
#pragma unroll
                for (int q = 0; q < 4; q++) rp[i * 4 + q] = c[i][q];
        }
        __syncthreads();
        if (wk == 0) {
            const float* rp = red + ((size_t)wm * 32 + lane) * 12;
#pragma unroll
            for (int q = 0; q < 4; q++) {
                int jj = (lane & 3) * 2 + (q & 1);
                int ja = j0 + jj;
                int b  = wm * 16 + (lane >> 2) + (q >> 1) * 8;
                float hr = c[0][q] + rp[0 * 4 + q] + bhh[ja];
                float hz = c[1][q] + rp[1 * 4 + q] + bhh[HDIM + ja];
                float hn = c[2][q] + rp[2 * 4 + q] + bhh[2 * HDIM + ja];
                float r = sigmoidf_(xr_[q] + hr);
                float z = sigmoidf_(xz_[q] + hz);
                float n = tanhf(xn_[q] + r * hn);
                float hnew = (1.f - z) * n + z * hp_[q];
                __nv_bfloat16 hh, hl;
                split2(hnew, hh, hl);
                sm_out[b * 8 + jj] = hh;
                sm_out[512 + b * 8 + jj] = hl;
            }
        }
        __syncthreads();

        // h_out store (swizzled chunk layout), barrier, then y
        uint4 v;
        int b_ = tid & 63, s_ = tid >> 6;
        if (tid < 128) {
            v = *(const uint4*)&sm_out[s_ * 512 + b_ * 8];
            int e = chn0 * 16384 + s_ * 8192 + b_ * 128 + ((g0 ^ (b_ & 7)) << 3);
            *(uint4*)&hdst[e] = v;
        }

        flag_barrier(bid, ++bar_t);

        if (tid < 128) {
            __nv_bfloat16* ydst = (s_ == 0 ? yhi : ylo);
            *(uint4*)&ydst[(size_t)t * NB * HDIM + b_ * HDIM + j0] = v;
        }
    }
}

// ---------------- output projection ------------------------------------------
__global__ void outproj_kernel(const __nv_bfloat16* __restrict__ xhi,
                               const __nv_bfloat16* __restrict__ xlo,
                               const float* __restrict__ W,
                               const float* __restrict__ b,
                               float* __restrict__ out) {
    int ln = blockIdx.x;
    __shared__ float xs[HDIM];
    const __nv_bfloat16* xh = xhi + (size_t)ln * HDIM;
    const __nv_bfloat16* xl = xlo + (size_t)ln * HDIM;
    for (int k = threadIdx.x; k < HDIM; k += 256)
        xs[k] = __bfloat162float(xh[k]) + __bfloat162float(xl[k]);
    __syncthreads();
    int warp = threadIdx.x >> 5, lane = threadIdx.x & 31;
    for (int c = warp; c < NC; c += 8) {
        const float* w = W + (size_t)c * HDIM;
        float acc = 0.f;
        for (int k = lane; k < HDIM; k += 32) acc = fmaf(xs[k], w[k], acc);
#pragma unroll
        for (int o = 16; o; o >>= 1) acc += __shfl_xor_sync(0xffffffffu, acc, o);
        if (lane == 0) out[(size_t)ln * NC + c] = acc + b[c];
    }
}

// ---------------- orchestration ---------------------------------------------
extern "C" void kernel_launch(void* const* d_in, const int* in_sizes, int n_in,
                              void* d_out, int out_size) {
    const float* inputs = (const float*)d_in[0];
    const float* emb_W  = (const float*)d_in[1];
    const float* emb_b  = (const float*)d_in[2];
    const float* w_ih   = (const float*)d_in[3];
    const float* w_hh   = (const float*)d_in[4];
    const float* b_ih   = (const float*)d_in[5];
    const float* b_hh   = (const float*)d_in[6];
    const float* out_W  = (const float*)d_in[7];
    const float* out_b  = (const float*)d_in[8];
    float* out = (float*)d_out;

    float *xg;
    __nv_bfloat16 *yhi, *ylo, *h2, *wih_hi, *wih_lo, *whh_hi, *whh_lo;
    cudaGetSymbolAddress((void**)&xg,     g_xg);
    cudaGetSymbolAddress((void**)&yhi,    g_y_hi);
    cudaGetSymbolAddress((void**)&ylo,    g_y_lo);
    cudaGetSymbolAddress((void**)&h2,     g_h2);
    cudaGetSymbolAddress((void**)&wih_hi, g_wih_hi);
    cudaGetSymbolAddress((void**)&wih_lo, g_wih_lo);
    cudaGetSymbolAddress((void**)&whh_hi, g_whh_hi);
    cudaGetSymbolAddress((void**)&whh_lo, g_whh_lo);

    cudaFuncSetAttribute(gru_layer_mma,
                         cudaFuncAttributeMaxDynamicSharedMemorySize, GRU_SMEM);

    const int M = LSEQ * NB;

    split_kernel<<<4096, 256>>>(w_ih, wih_hi, wih_lo, NL * H3 * EDIM);
    split_kernel<<<4096, 256>>>(w_hh, whh_hi, whh_lo, NL * H3 * HDIM);

    {
        dim3 grid(M, EDIM / 256);
        embed_kernel<<<grid, 256>>>(inputs, emb_W, emb_b, yhi, ylo);
    }

    for (int l = 0; l < NL; l++) {
        {
            dim3 grid(H3 / 64, M / 128);
            gemm_xg_mma<<<grid, 256>>>(yhi, ylo,
                                       wih_hi + (size_t)l * H3 * EDIM,
                                       wih_lo + (size_t)l * H3 * EDIM,
                                       b_ih + (size_t)l * H3,
                                       xg);
        }
        gru_layer_mma<<<GRU_BLOCKS, 256, GRU_SMEM>>>(
            xg,
            whh_hi + (size_t)l * H3 * HDIM,
            whh_lo + (size_t)l * H3 * HDIM,
            b_hh + (size_t)l * H3,
            h2, yhi, ylo);
    }

    outproj_kernel<<<M, 256>>>(yhi, ylo, out_W, out_b, out);

    (void)in_sizes; (void)n_in; (void)out_size;
}

// round 16
// speedup vs baseline: 1.0700x; 1.0700x over previous
#include <cuda_runtime.h>
#include <cuda_bf16.h>
#include <math.h>
#include <stdint.h>

#define LSEQ 512
#define NB   64
#define KIN  38
#define EDIM 1024
#define HDIM 1024
#define NL   3
#define NC   38
#define H3   (3*HDIM)

#define GRU_BLOCKS 128
#define WS_LD 1032

// gru smem byte offsets
#define MB0_OFF   0
#define MB1_OFF   8
#define WS_HI_OFF 16
#define WS_LO_OFF (WS_HI_OFF + 24*WS_LD*2)     // 49552
#define HB_OFF    (WS_LO_OFF + 24*WS_LD*2)     // 99088
#define RED_OFF   (HB_OFF + 2*32768)           // 164624
#define SMOUT_OFF (RED_OFF + 6144)             // 170768
#define GRU_SMEM  (SMOUT_OFF + 2048)           // 172816

// h2 layout: [slot(2)][chunk(8)][split(2)][row(64)][col(128)] bf16,
// groups of 8 cols xor-swizzled by (row&7).
#define H2_SLOT 131072

// ---------------- scratch (device globals; no allocations allowed) ----------
__device__ __align__(16) float         g_xg[(size_t)LSEQ * NB * H3];
__device__ __align__(16) __nv_bfloat16 g_y_hi[(size_t)LSEQ * NB * EDIM];
__device__ __align__(16) __nv_bfloat16 g_y_lo[(size_t)LSEQ * NB * EDIM];
__device__ __align__(16) __nv_bfloat16 g_h2[2 * H2_SLOT];
__device__ __align__(16) __nv_bfloat16 g_wih_hi[(size_t)NL * H3 * EDIM];
__device__ __align__(16) __nv_bfloat16 g_wih_lo[(size_t)NL * H3 * EDIM];
__device__ __align__(16) __nv_bfloat16 g_whh_hi[(size_t)NL * H3 * HDIM];
__device__ __align__(16) __nv_bfloat16 g_whh_lo[(size_t)NL * H3 * HDIM];

// barrier flags (monotonic; generation derived from flag value => replay-safe)
__device__ unsigned g_flags[GRU_BLOCKS];

__device__ __forceinline__ void flag_barrier(int bid, unsigned target) {
    __syncthreads();
    if (threadIdx.x == 0) {
        __threadfence();
        ((volatile unsigned*)g_flags)[bid] = target;
    }
    if (threadIdx.x < 32) {
        bool done = false;
        while (!done) {
            bool ok = true;
#pragma unroll
            for (int q = 0; q < 4; q++) {
                unsigned v = ((volatile unsigned*)g_flags)[threadIdx.x + q * 32];
                if ((int)(v - target) < 0) ok = false;
            }
            done = __all_sync(0xffffffffu, ok);
        }
    }
    __syncthreads();
}

// ---------------- helpers ------------------------------------------------------
__device__ __forceinline__ uint32_t smem_u32(const void* p) {
    return (uint32_t)__cvta_generic_to_shared(p);
}
__device__ __forceinline__ void ldsm_x4(uint32_t* r, uint32_t addr) {
    asm volatile("ldmatrix.sync.aligned.m8n8.x4.shared.b16 {%0,%1,%2,%3},[%4];"
                 : "=r"(r[0]), "=r"(r[1]), "=r"(r[2]), "=r"(r[3]) : "r"(addr));
}
__device__ __forceinline__ void mma16816(float* c, const uint32_t* a,
                                         uint32_t b0, uint32_t b1) {
    asm volatile(
        "mma.sync.aligned.m16n8k16.row.col.f32.bf16.bf16.f32 "
        "{%0,%1,%2,%3},{%4,%5,%6,%7},{%8,%9},{%0,%1,%2,%3};"
        : "+f"(c[0]), "+f"(c[1]), "+f"(c[2]), "+f"(c[3])
        : "r"(a[0]), "r"(a[1]), "r"(a[2]), "r"(a[3]), "r"(b0), "r"(b1));
}
__device__ __forceinline__ void bulk_copy(uint32_t dst_smem, const void* src,
                                          uint32_t bytes, uint32_t mbar) {
    asm volatile(
        "cp.async.bulk.shared::cluster.global.mbarrier::complete_tx::bytes "
        "[%0], [%1], %2, [%3];"
        :: "r"(dst_smem), "l"(__cvta_generic_to_global(src)), "r"(bytes), "r"(mbar)
        : "memory");
}
#define MBARRIER_INIT(mb, cnt) \
    asm volatile("mbarrier.init.shared.b64 [%0], %1;" :: "r"((uint32_t)(mb)), "r"((uint32_t)(cnt)) : "memory")
#define MBARRIER_EXPECT_TX(mb, tx) \
    asm volatile("mbarrier.arrive.expect_tx.shared.b64 _, [%0], %1;" \
                 :: "r"((uint32_t)(mb)), "r"((uint32_t)(tx)) : "memory")
#define MBARRIER_WAIT_PARITY(mb, ph) do { \
    uint32_t _mb = (uint32_t)(mb), _ph = (uint32_t)(ph), _done; \
    asm volatile("{\n\t.reg .pred p;\n\t" \
        "mbarrier.try_wait.parity.acquire.cta.shared::cta.b64 p, [%1], %2;\n\t" \
        "selp.b32 %0, 1, 0, p;\n\t}" : "=r"(_done) : "r"(_mb), "r"(_ph) : "memory"); \
    if (!_done) { \
        asm volatile("{\n\t.reg .pred P1;\n\t" \
            "WAIT_LOOP_%=:\n\t" \
            "mbarrier.try_wait.parity.acquire.cta.shared::cta.b64 P1, [%0], %1, 0x989680;\n\t" \
            "@P1 bra.uni WAIT_DONE_%=;\n\tbra.uni WAIT_LOOP_%=;\n\tWAIT_DONE_%=:\n\t}" \
            :: "r"(_mb), "r"(_ph) : "memory"); \
    } \
} while (0)

__device__ __forceinline__ void split2(float x, __nv_bfloat16& hi, __nv_bfloat16& lo) {
    hi = __float2bfloat16(x);
    lo = __float2bfloat16(x - __bfloat162float(hi));
}
__device__ __forceinline__ float sigmoidf_(float x) {
    return 1.f / (1.f + expf(-x));
}

// ---------------- weight split ----------------------------------------------
__global__ void split_kernel(const float* __restrict__ src,
                             __nv_bfloat16* __restrict__ hi,
                             __nv_bfloat16* __restrict__ lo, int n) {
    for (int i = blockIdx.x * 256 + threadIdx.x; i < n; i += gridDim.x * 256) {
        float x = src[i];
        __nv_bfloat16 h = __float2bfloat16(x);
        hi[i] = h;
        lo[i] = __float2bfloat16(x - __bfloat162float(h));
    }
}

// ---------------- embedding ---------------------------------------------------
__global__ void embed_kernel(const float* __restrict__ in,
                             const float* __restrict__ W,
                             const float* __restrict__ b,
                             __nv_bfloat16* __restrict__ yhi,
                             __nv_bfloat16* __restrict__ ylo) {
    int ln = blockIdx.x;
    int e  = blockIdx.y * 256 + threadIdx.x;
    __shared__ float xs[KIN];
    if (threadIdx.x < KIN) xs[threadIdx.x] = in[(size_t)ln * KIN + threadIdx.x];
    __syncthreads();
    float acc = b[e];
    const float* w = W + (size_t)e * KIN;
#pragma unroll
    for (int k = 0; k < KIN; k++) acc = fmaf(xs[k], w[k], acc);
    __nv_bfloat16 hh, hl;
    split2(acc, hh, hl);
    yhi[(size_t)ln * EDIM + e] = hh;
    ylo[(size_t)ln * EDIM + e] = hl;
}

// ---------------- bf16-split MMA GEMM (input projections) --------------------
__global__ void __launch_bounds__(256)
gemm_xg_mma(const __nv_bfloat16* __restrict__ Ahi,
            const __nv_bfloat16* __restrict__ Alo,
            const __nv_bfloat16* __restrict__ Bhi,
            const __nv_bfloat16* __restrict__ Blo,
            const float* __restrict__ bias,
            float* __restrict__ C) {
    __shared__ __nv_bfloat16 sA[2][128][40];
    __shared__ __nv_bfloat16 sB[2][64][40];
    const int tid = threadIdx.x, lane = tid & 31, warp = tid >> 5;
    const int wm = warp >> 1, wn = warp & 1;
    const int bm = blockIdx.y * 128, bn = blockIdx.x * 64;

    float c[2][4][4];
#pragma unroll
    for (int m = 0; m < 2; m++)
#pragma unroll
        for (int n = 0; n < 4; n++)
#pragma unroll
            for (int q = 0; q < 4; q++) c[m][n][q] = 0.f;

    for (int k0 = 0; k0 < EDIM; k0 += 32) {
        __syncthreads();
        for (int i = tid; i < 512; i += 256) {
            int r = i >> 2, cv = i & 3;
            *(uint4*)&sA[0][r][cv * 8] = *(const uint4*)(Ahi + (size_t)(bm + r) * EDIM + k0 + cv * 8);
            *(uint4*)&sA[1][r][cv * 8] = *(const uint4*)(Alo + (size_t)(bm + r) * EDIM + k0 + cv * 8);
        }
        if (tid < 256) {
            int r = tid >> 2, cv = tid & 3;
            *(uint4*)&sB[0][r][cv * 8] = *(const uint4*)(Bhi + (size_t)(bn + r) * EDIM + k0 + cv * 8);
            *(uint4*)&sB[1][r][cv * 8] = *(const uint4*)(Blo + (size_t)(bn + r) * EDIM + k0 + cv * 8);
        }
        __syncthreads();

        uint32_t a[2][2][2][4];
#pragma unroll
        for (int s = 0; s < 2; s++)
#pragma unroll
            for (int m = 0; m < 2; m++) {
                int arow = wm * 32 + m * 16 + (lane & 15);
                int acol = (lane >> 4) * 8;
                uint32_t ad = smem_u32(&sA[s][arow][acol]);
                ldsm_x4(a[s][m][0], ad);
                ldsm_x4(a[s][m][1], ad + 32);
            }
        uint32_t bf[2][4][4];
#pragma unroll
        for (int s = 0; s < 2; s++)
#pragma unroll
            for (int n = 0; n < 4; n++) {
                int brow = wn * 32 + n * 8 + (lane & 7);
                int bcol = (lane >> 3) * 8;
                ldsm_x4(bf[s][n], smem_u32(&sB[s][brow][bcol]));
            }
#pragma unroll
        for (int m = 0; m < 2; m++)
#pragma unroll
            for (int n = 0; n < 4; n++)
#pragma unroll
                for (int k = 0; k < 2; k++) {
                    mma16816(c[m][n], a[0][m][k], bf[0][n][k * 2], bf[0][n][k * 2 + 1]);
                    mma16816(c[m][n], a[0][m][k], bf[1][n][k * 2], bf[1][n][k * 2 + 1]);
                    mma16816(c[m][n], a[1][m][k], bf[0][n][k * 2], bf[0][n][k * 2 + 1]);
                }
    }

#pragma unroll
    for (int m = 0; m < 2; m++) {
        int row0 = bm + wm * 32 + m * 16 + (lane >> 2);
#pragma unroll
        for (int n = 0; n < 4; n++) {
            int col = bn + wn * 32 + n * 8 + (lane & 3) * 2;
            float2 bb = *(const float2*)(bias + col);
            float2 v0 = make_float2(c[m][n][0] + bb.x, c[m][n][1] + bb.y);
            float2 v1 = make_float2(c[m][n][2] + bb.x, c[m][n][3] + bb.y);
            *(float2*)(C + (size_t)row0 * H3 + col) = v0;
            *(float2*)(C + (size_t)(row0 + 8) * H3 + col) = v1;
        }
    }
}

// ---------------- persistent GRU layer: bulk-DMA staged h ---------------------
// 256 threads (8 warps: 4 wm x 2 wk). Block owns 8 hidden cols (24 W rows,
// resident in smem). h broadcast: 8 chunks x 32KB per step, each ONE
// cp.async.bulk into a double buffer, completion via mbarrier.
__global__ void __launch_bounds__(256, 1)
gru_layer_mma(const float* __restrict__ xg,
              const __nv_bfloat16* __restrict__ whh_hi,
              const __nv_bfloat16* __restrict__ whh_lo,
              const float* __restrict__ bhh,
              __nv_bfloat16* __restrict__ h2,
              __nv_bfloat16* __restrict__ yhi,
              __nv_bfloat16* __restrict__ ylo) {
    extern __shared__ __align__(16) char smem[];
    __nv_bfloat16* ws_hi  = (__nv_bfloat16*)(smem + WS_HI_OFF);
    __nv_bfloat16* ws_lo  = (__nv_bfloat16*)(smem + WS_LO_OFF);
    float*         red    = (float*)(smem + RED_OFF);
    __nv_bfloat16* sm_out = (__nv_bfloat16*)(smem + SMOUT_OFF);
    const uint32_t smem_base = smem_u32(smem);
    const uint32_t hb_base = smem_base + HB_OFF;
    const uint32_t mb0 = smem_base + MB0_OFF;
    const uint32_t mb1 = smem_base + MB1_OFF;

    const int tid  = threadIdx.x;
    const int lane = tid & 31, warp = tid >> 5;
    const int wm = warp & 3, wk = warp >> 2;
    const int bid = blockIdx.x;
    const int j0 = bid * 8;
    const int g0 = (j0 >> 3) & 15;      // 16B group of this block's cols
    const int chn0 = j0 >> 7;           // chunk of this block's cols

    if (tid == 0) {
        MBARRIER_INIT(mb0, 1);
        MBARRIER_INIT(mb1, 1);
    }

    // W tile -> smem (rows r = g*8+jj -> global row g*HDIM + j0 + jj)
    for (int i = tid; i < 24 * 128; i += 256) {
        int r = i >> 7, v = i & 127;
        int grow = (r >> 3) * HDIM + j0 + (r & 7);
        *(uint4*)&ws_hi[r * WS_LD + v * 8] = *(const uint4*)(whh_hi + (size_t)grow * HDIM + v * 8);
        *(uint4*)&ws_lo[r * WS_LD + v * 8] = *(const uint4*)(whh_lo + (size_t)grow * HDIM + v * 8);
    }
    // zero h slot 0: block zeros its 1024-element slice
    *(uint2*)&h2[bid * 1024 + tid * 4] = make_uint2(0u, 0u);
    __syncthreads();

    unsigned bar_t = ((volatile unsigned*)g_flags)[bid];
    flag_barrier(bid, ++bar_t);

    int wc0 = 0, wc1 = 0;

    for (int t = 0; t < LSEQ; t++) {
        const __nv_bfloat16* hsrc = h2 + (size_t)(t & 1) * H2_SLOT;
        __nv_bfloat16* hdst = h2 + (size_t)((t + 1) & 1) * H2_SLOT;
        const float* xg_t = xg + (size_t)t * NB * H3;

        // kick off chunk 0 bulk copy
        if (tid == 0) {
            MBARRIER_EXPECT_TX(mb0, 32768);
            bulk_copy(hb_base, hsrc, 32768, mb0);
        }

        // prefetch epilogue operands (wk==0 warps do gates)
        float xr_[4], xz_[4], xn_[4], hp_[4];
        if (wk == 0) {
#pragma unroll
            for (int q = 0; q < 4; q++) {
                int b  = wm * 16 + (lane >> 2) + (q >> 1) * 8;
                int ja = j0 + (lane & 3) * 2 + (q & 1);
                const float* xr = xg_t + (size_t)b * H3 + ja;
                xr_[q] = xr[0];
                xz_[q] = xr[HDIM];
                xn_[q] = xr[2 * HDIM];
                int e = chn0 * 16384 + b * 128 + ((g0 ^ (b & 7)) << 3) + (ja & 7);
                hp_[q] = __bfloat162float(hsrc[e]) + __bfloat162float(hsrc[e + 8192]);
            }
        }

        float c[3][4];
#pragma unroll
        for (int i = 0; i < 3; i++)
#pragma unroll
            for (int q = 0; q < 4; q++) c[i][q] = 0.f;

        for (int ch = 0; ch < 8; ch++) {
            const int buf = ch & 1;
            // issue next chunk into the other buffer (free since chunk ch-1)
            if (ch < 7 && tid == 0) {
                uint32_t mbn = (buf == 0) ? mb1 : mb0;
                MBARRIER_EXPECT_TX(mbn, 32768);
                bulk_copy(hb_base + (1 - buf) * 32768,
                          hsrc + (size_t)(ch + 1) * 16384, 32768, mbn);
            }
            if (buf == 0) { MBARRIER_WAIT_PARITY(mb0, wc0 & 1); wc0++; }
            else          { MBARRIER_WAIT_PARITY(mb1, wc1 & 1); wc1++; }

            const uint32_t bufb = hb_base + buf * 32768;
            const int arow = wm * 16 + (lane & 15);
            const int rx = arow & 7;
            const uint32_t rowb = bufb + arow * 256;
#pragma unroll
            for (int k32 = 0; k32 < 2; k32++) {
                const int gb = wk * 8 + k32 * 4 + (lane >> 4);
                uint32_t a0 = rowb + (uint32_t)((gb ^ rx) << 4);
                uint32_t a1 = rowb + (uint32_t)(((gb + 2) ^ rx) << 4);
                uint32_t a_hi[2][4], a_lo[2][4];
                ldsm_x4(a_hi[0], a0);          ldsm_x4(a_hi[1], a1);
                ldsm_x4(a_lo[0], a0 + 16384);  ldsm_x4(a_lo[1], a1 + 16384);

                uint32_t b_hi[3][4], b_lo[3][4];
                int bkcol = ch * 128 + wk * 64 + k32 * 32 + (lane >> 3) * 8;
#pragma unroll
                for (int n8 = 0; n8 < 3; n8++) {
                    int brow = n8 * 8 + (lane & 7);
                    ldsm_x4(b_hi[n8], smem_u32(&ws_hi[brow * WS_LD + bkcol]));
                    ldsm_x4(b_lo[n8], smem_u32(&ws_lo[brow * WS_LD + bkcol]));
                }
#pragma unroll
                for (int n8 = 0; n8 < 3; n8++)
#pragma unroll
                    for (int k = 0; k < 2; k++) {
                        mma16816(c[n8], a_hi[k], b_hi[n8][k * 2], b_hi[n8][k * 2 + 1]);
                        mma16816(c[n8], a_hi[k], b_lo[n8][k * 2], b_lo[n8][k * 2 + 1]);
                        mma16816(c[n8], a_lo[k], b_hi[n8][k * 2], b_hi[n8][k * 2 + 1]);
                    }
            }
            __syncthreads();   // all warps done reading buf -> refillable
        }

        // combine k-halves
        if (wk == 1) {
            float* rp = red + ((size_t)wm * 32 + lane) * 12;
#pragma unroll
            for (int i = 0; i < 3; i++)
#pragma unroll
                for (int q = 0; q < 4; q++) rp[i * 4 + q] = c[i][q];
        }
        __syncthreads();
        if (wk == 0) {
            const float* rp = red + ((size_t)wm * 32 + lane) * 12;
#pragma unroll
            for (int q = 0; q < 4; q++) {
                int jj = (lane & 3) * 2 + (q & 1);
                int ja = j0 + jj;
                int b  = wm * 16 + (lane >> 2) + (q >> 1) * 8;
                float hr = c[0][q] + rp[0 * 4 + q] + bhh[ja];
                float hz = c[1][q] + rp[1 * 4 + q] + bhh[HDIM + ja];
                float hn = c[2][q] + rp[2 * 4 + q] + bhh[2 * HDIM + ja];
                float r = sigmoidf_(xr_[q] + hr);
                float z = sigmoidf_(xz_[q] + hz);
                float n = tanhf(xn_[q] + r * hn);
                float hnew = (1.f - z) * n + z * hp_[q];
                __nv_bfloat16 hh, hl;
                split2(hnew, hh, hl);
                sm_out[b * 8 + jj] = hh;
                sm_out[512 + b * 8 + jj] = hl;
            }
        }
        __syncthreads();

        // h_out store (swizzled chunk layout), barrier, then y
        uint4 v;
        int b_ = tid & 63, s_ = tid >> 6;
        if (tid < 128) {
            v = *(const uint4*)&sm_out[s_ * 512 + b_ * 8];
            int e = chn0 * 16384 + s_ * 8192 + b_ * 128 + ((g0 ^ (b_ & 7)) << 3);
            *(uint4*)&hdst[e] = v;
        }

        flag_barrier(bid, ++bar_t);

        if (tid < 128) {
            __nv_bfloat16* ydst = (s_ == 0 ? yhi : ylo);
            *(uint4*)&ydst[(size_t)t * NB * HDIM + b_ * HDIM + j0] = v;
        }
    }
}

// ---------------- output projection ------------------------------------------
__global__ void outproj_kernel(const __nv_bfloat16* __restrict__ xhi,
                               const __nv_bfloat16* __restrict__ xlo,
                               const float* __restrict__ W,
                               const float* __restrict__ b,
                               float* __restrict__ out) {
    int ln = blockIdx.x;
    __shared__ float xs[HDIM];
    const __nv_bfloat16* xh = xhi + (size_t)ln * HDIM;
    const __nv_bfloat16* xl = xlo + (size_t)ln * HDIM;
    for (int k = threadIdx.x; k < HDIM; k += 256)
        xs[k] = __bfloat162float(xh[k]) + __bfloat162float(xl[k]);
    __syncthreads();
    int warp = threadIdx.x >> 5, lane = threadIdx.x & 31;
    for (int c = warp; c < NC; c += 8) {
        const float* w = W + (size_t)c * HDIM;
        float acc = 0.f;
        for (int k = lane; k < HDIM; k += 32) acc = fmaf(xs[k], w[k], acc);
#pragma unroll
        for (int o = 16; o; o >>= 1) acc += __shfl_xor_sync(0xffffffffu, acc, o);
        if (lane == 0) out[(size_t)ln * NC + c] = acc + b[c];
    }
}

// ---------------- orchestration ---------------------------------------------
extern "C" void kernel_launch(void* const* d_in, const int* in_sizes, int n_in,
                              void* d_out, int out_size) {
    const float* inputs = (const float*)d_in[0];
    const float* emb_W  = (const float*)d_in[1];
    const float* emb_b  = (const float*)d_in[2];
    const float* w_ih   = (const float*)d_in[3];
    const float* w_hh   = (const float*)d_in[4];
    const float* b_ih   = (const float*)d_in[5];
    const float* b_hh   = (const float*)d_in[6];
    const float* out_W  = (const float*)d_in[7];
    const float* out_b  = (const float*)d_in[8];
    float* out = (float*)d_out;

    float *xg;
    __nv_bfloat16 *yhi, *ylo, *h2, *wih_hi, *wih_lo, *whh_hi, *whh_lo;
    cudaGetSymbolAddress((void**)&xg,     g_xg);
    cudaGetSymbolAddress((void**)&yhi,    g_y_hi);
    cudaGetSymbolAddress((void**)&ylo,    g_y_lo);
    cudaGetSymbolAddress((void**)&h2,     g_h2);
    cudaGetSymbolAddress((void**)&wih_hi, g_wih_hi);
    cudaGetSymbolAddress((void**)&wih_lo, g_wih_lo);
    cudaGetSymbolAddress((void**)&whh_hi, g_whh_hi);
    cudaGetSymbolAddress((void**)&whh_lo, g_whh_lo);

    cudaFuncSetAttribute(gru_layer_mma,
                         cudaFuncAttributeMaxDynamicSharedMemorySize, GRU_SMEM);

    const int M = LSEQ * NB;

    split_kernel<<<4096, 256>>>(w_ih, wih_hi, wih_lo, NL * H3 * EDIM);
    split_kernel<<<4096, 256>>>(w_hh, whh_hi, whh_lo, NL * H3 * HDIM);

    {
        dim3 grid(M, EDIM / 256);
        embed_kernel<<<grid, 256>>>(inputs, emb_W, emb_b, yhi, ylo);
    }

    for (int l = 0; l < NL; l++) {
        {
            dim3 grid(H3 / 64, M / 128);
            gemm_xg_mma<<<grid, 256>>>(yhi, ylo,
                                       wih_hi + (size_t)l * H3 * EDIM,
                                       wih_lo + (size_t)l * H3 * EDIM,
                                       b_ih + (size_t)l * H3,
                                       xg);
        }
        gru_layer_mma<<<GRU_BLOCKS, 256, GRU_SMEM>>>(
            xg,
            whh_hi + (size_t)l * H3 * HDIM,
            whh_lo + (size_t)l * H3 * HDIM,
            b_hh + (size_t)l * H3,
            h2, yhi, ylo);
    }

    outproj_kernel<<<M, 256>>>(yhi, ylo, out_W, out_b, out);

    (void)in_sizes; (void)n_in; (void)out_size;
}